// round 13
// baseline (speedup 1.0000x reference)
#include <cuda_runtime.h>
#include <cstdint>

#define VOCAB  50257
#define VPAD   50688          // 99 * 512
#define NTOK   4096
#define TM     32             // tokens per CTA
#define TN     512            // vocab candidates per chunk
#define KC     16             // k-chunk
#define NKC    12             // 192/16
#define TOPK   10

// dynamic smem layout (float offsets)
#define OFF_XS 0              // [192][36]  x reduced, transposed, *4
#define OFF_BS 6912           // [2][16][512] double-buffered er chunk
#define OFF_LG 23296          // [256][20]  quarter logit tile (aligned stride)
#define LG_STR 20
#define SMEM_FLOATS (OFF_LG + 256 * LG_STR)     // 28416
#define SMEM_MAIN (SMEM_FLOATS * 4)             // 113,664 B -> 2 CTAs/SM
#define SMEM_FIN  (25536 * 4)

// reduced embeddings, transposed [k][v], zero-padded to VPAD
__device__ float g_ert[(size_t)192 * VPAD];
__device__ float g_pv[2][NTOK][TOPK];
__device__ int   g_pi[2][NTOK][TOPK];
__device__ float g_ps[2][NTOK];

__device__ __forceinline__ void cp16(float* s, const float* g) {
    unsigned sa = (unsigned)__cvta_generic_to_shared(s);
    asm volatile("cp.async.cg.shared.global [%0], [%1], 16;" :: "r"(sa), "l"(g));
}
__device__ __forceinline__ unsigned long long pack2(float v) {
    unsigned long long r;
    asm("mov.b64 %0, {%1, %2};" : "=l"(r) : "f"(v), "f"(v));
    return r;
}
__device__ __forceinline__ void fma2(unsigned long long& d, unsigned long long a, unsigned long long b) {
    asm("fma.rn.f32x2 %0, %1, %2, %0;" : "+l"(d) : "l"(a), "l"(b));
}
__device__ __forceinline__ void tk_insert(float v, int gi, float* tv, int* ti_, float& minv, int& minp) {
    tv[minp] = v; ti_[minp] = gi;
    minv = tv[0]; minp = 0;
#pragma unroll
    for (int q = 1; q < TOPK; q++) if (tv[q] < minv) { minv = tv[q]; minp = q; }
}

// ---------- prep: g_ert[k][v] = emb[v][4k] ----------
__global__ void __launch_bounds__(256)
prep_kernel(const float* __restrict__ emb) {
    __shared__ float smp[48][193];
    const int vb = blockIdx.x * 48;
    for (int idx = threadIdx.x; idx < 48 * 192; idx += 256) {
        int vl = idx / 192, k = idx - vl * 192;
        int v = vb + vl;
        smp[vl][k] = (v < VOCAB) ? emb[(size_t)v * 768 + 4 * k] : 0.0f;
    }
    __syncthreads();
    for (int idx = threadIdx.x; idx < 48 * 192; idx += 256) {
        int k = idx / 48, vl = idx - k * 48;
        g_ert[(size_t)k * VPAD + vb + vl] = smp[vl][k];
    }
}

// ---------- main: FFMA2 GEMM (conflict-free B loads) + fused softmax-sum + top-k ----------
__global__ void __launch_bounds__(256, 2)
main_kernel(const float* __restrict__ x) {
    extern __shared__ float sm[];
    float* XS = sm + OFF_XS;
    float* BS = sm + OFF_BS;
    float* LG = sm + OFF_LG;
    const int tid = threadIdx.x;
    const int ty = tid >> 6;        // 0..3  (8-token row group)
    const int tx = tid & 63;        // 0..63
    const int mt = blockIdx.x >> 1, sp = blockIdx.x & 1;
    const int m0 = mt * TM;
    const int chb = sp ? 50 : 0, che = sp ? 99 : 50;

    // stage x reduced (transposed [k][m], scale 4 = sqrt(R)^2 folded in)
    for (int idx = tid; idx < TM * 192; idx += 256) {
        int m = idx / 192, k = idx - m * 192;
        XS[k * 36 + m] = 4.0f * x[(size_t)(m0 + m) * 768 + 4 * k];
    }

    // per-thread scan state: token sM = tid>>3, scanner slot sS = tid&7
    float tv[TOPK]; int ti_[TOPK];
#pragma unroll
    for (int i = 0; i < TOPK; i++) { tv[i] = -1e30f; ti_[i] = 0; }
    float minv = -1e30f; int minp = 0;
    float sumexp = 0.0f;
    const int sS = tid & 7;

    __syncthreads();

    // preload chunk chb, kc=0 into buffer 0
    {
        const float* src = g_ert + chb * TN;
#pragma unroll
        for (int i = 0; i < 8; i++) {
            int pos = i * 256 + tid;
            int r = pos >> 7, c4 = (pos & 127) << 2;
            cp16(BS + r * TN + c4, src + (size_t)r * VPAD + c4);
        }
        asm volatile("cp.async.commit_group;" ::: "memory");
    }

    for (int ch = chb; ch < che; ch++) {
        const int c0 = ch * TN;
        // acc[i][0..1] = cands 4tx..4tx+3 ; acc[i][2..3] = cands 256+4tx..+3
        unsigned long long acc[8][4];
#pragma unroll
        for (int i = 0; i < 8; i++)
#pragma unroll
            for (int j = 0; j < 4; j++) acc[i][j] = 0ull;

        for (int kc = 0; kc < NKC; kc++) {
            if (kc + 1 < NKC) {
                const float* src = g_ert + (size_t)(kc + 1) * KC * VPAD + c0;
                float* dst = BS + ((kc + 1) & 1) * (KC * TN);
#pragma unroll
                for (int i = 0; i < 8; i++) {
                    int pos = i * 256 + tid;
                    int r = pos >> 7, c4 = (pos & 127) << 2;
                    cp16(dst + r * TN + c4, src + (size_t)r * VPAD + c4);
                }
                asm volatile("cp.async.commit_group;" ::: "memory");
                asm volatile("cp.async.wait_group 1;" ::: "memory");
            } else {
                asm volatile("cp.async.wait_group 0;" ::: "memory");
            }
            __syncthreads();
            const float* Bp = BS + (kc & 1) * (KC * TN) + (tx << 2);   // 16B/lane: conflict-free
            const float* Ap = XS + kc * KC * 36 + (ty << 3);
#pragma unroll 4
            for (int k = 0; k < KC; k++) {
                const float4 a0 = *(const float4*)(Ap + k * 36);
                const float4 a1 = *(const float4*)(Ap + k * 36 + 4);
                const ulonglong2 b01 = *(const ulonglong2*)(Bp + (k << 9));          // cands 4tx..4tx+3
                const ulonglong2 b23 = *(const ulonglong2*)(Bp + (k << 9) + 256);    // cands 256+4tx..+3
                unsigned long long bb[4] = {b01.x, b01.y, b23.x, b23.y};
                float av[8] = {a0.x, a0.y, a0.z, a0.w, a1.x, a1.y, a1.z, a1.w};
#pragma unroll
                for (int i = 0; i < 8; i++) {
                    unsigned long long ap = pack2(av[i]);
#pragma unroll
                    for (int j = 0; j < 4; j++) fma2(acc[i][j], ap, bb[j]);
                }
            }
            __syncthreads();
        }

        // prefetch next chunk's kc=0 during the scan phase (overlap)
        if (ch + 1 < che) {
            const float* src = g_ert + (size_t)(ch + 1) * TN;
#pragma unroll
            for (int i = 0; i < 8; i++) {
                int pos = i * 256 + tid;
                int r = pos >> 7, c4 = (pos & 127) << 2;
                cp16(BS + r * TN + c4, src + (size_t)r * VPAD + c4);
            }
            asm volatile("cp.async.commit_group;" ::: "memory");
        }

        // spill + scan in 4 quarters of 128 columns
        // quarter q covers global cols [q*128, q*128+128):
        //   group g = q>>1 (acc pair 2g,2g+1), half h = q&1 (tx<32 vs tx>=32)
        const int txh = tx >> 5;          // which half this thread's cands are in
        const int slot = (tx & 31) >> 2;  // scanner slot of this thread's cols
        const int cb = (tx & 3) << 2;     // col base within the scanner's 16 (16B aligned)
#pragma unroll 1
        for (int q = 0; q < 4; q++) {
            if (txh == (q & 1)) {
                const int g2 = (q >> 1) << 1;
#pragma unroll
                for (int i = 0; i < 8; i++) {
                    float* dst = LG + ((((ty << 3) + i) << 3) + slot) * LG_STR + cb;
                    *(ulonglong2*)dst = make_ulonglong2(acc[i][g2], acc[i][g2 + 1]);
                }
            }
            __syncthreads();
            {
                const float* row = LG + tid * LG_STR;
                const int gb = c0 + (q << 7) + (sS << 4);
#pragma unroll
                for (int c = 0; c < 16; c++) {
                    float l = row[c];
                    int n_g = gb + c;
                    if (n_g < VOCAB) {
                        sumexp += __expf(l);
                        if (l > minv) tk_insert(l, n_g, tv, ti_, minv, minp);
                    }
                }
            }
            __syncthreads();
        }
    }

    // dump per-scanner state (overlay on XS region) and merge 8 scanners/token
    float* MV = sm;
    int*   MI = (int*)(sm + 2560);
    float* MS = sm + 5120;
#pragma unroll
    for (int i = 0; i < TOPK; i++) { MV[tid * TOPK + i] = tv[i]; MI[tid * TOPK + i] = ti_[i]; }
    MS[tid] = sumexp;
    __syncthreads();
    if (tid < TM) {
        const int m = tid;
        float bv[TOPK]; int bi[TOPK];
#pragma unroll
        for (int j = 0; j < TOPK; j++) { bv[j] = MV[m * 80 + j]; bi[j] = MI[m * 80 + j]; }
        float bmin = bv[0]; int bmp = 0;
#pragma unroll
        for (int q = 1; q < TOPK; q++) if (bv[q] < bmin) { bmin = bv[q]; bmp = q; }
        for (int e = TOPK; e < 8 * TOPK; e++) {
            float v = MV[m * 80 + e];
            if (v > bmin) tk_insert(v, MI[m * 80 + e], bv, bi, bmin, bmp);
        }
        float S = 0.0f;
#pragma unroll
        for (int s = 0; s < 8; s++) S += MS[m * 8 + s];
        int t = m0 + m;
#pragma unroll
        for (int j = 0; j < TOPK; j++) { g_pv[sp][t][j] = bv[j]; g_pi[sp][t][j] = bi[j]; }
        g_ps[sp][t] = S;
    }
}

// ---------- finalize: merge 2 splits, exact rescore, output ----------
__global__ void __launch_bounds__(256)
final_kernel(const float* __restrict__ x, const float* __restrict__ emb,
             float* __restrict__ out) {
    extern __shared__ float sm2[];
    float* XF = sm2;                        // [32][768]
    int*   CI = (int*)(sm2 + 24576);        // [320]
    float* CS = sm2 + 24896;                // [320]
    float* EX = sm2 + 25216;                // [320]
    const int tid = threadIdx.x;
    const int t0 = blockIdx.x * 32;

    if (tid < 32) {
        int t = t0 + tid;
        float bv[TOPK]; int bi[TOPK];
#pragma unroll
        for (int j = 0; j < TOPK; j++) { bv[j] = g_pv[0][t][j]; bi[j] = g_pi[0][t][j]; }
        float bmin = bv[0]; int bmp = 0;
#pragma unroll
        for (int q = 1; q < TOPK; q++) if (bv[q] < bmin) { bmin = bv[q]; bmp = q; }
#pragma unroll
        for (int e = 0; e < TOPK; e++) {
            float v2 = g_pv[1][t][e];
            if (v2 > bmin) tk_insert(v2, g_pi[1][t][e], bv, bi, bmin, bmp);
        }
        float S = g_ps[0][t] + g_ps[1][t];
        float invS = 1.0f / S;
#pragma unroll
        for (int j = 0; j < TOPK; j++) {
            CI[tid * TOPK + j] = bi[j];
            CS[tid * TOPK + j] = __expf(bv[j]) * invS;
        }
    }
    __syncthreads();

    for (int idx = tid; idx < 32 * 768; idx += 256)
        XF[idx] = x[(size_t)t0 * 768 + idx];
    __syncthreads();

    // exact rescore: 320 (token,cand) pairs, 8 lanes per pair, coalesced gather
#pragma unroll 1
    for (int it = 0; it < 10; it++) {
        int slot = it * 256 + tid;
        int p = slot >> 3, q = slot & 7;
        int e = CI[p];
        const float4* er = (const float4*)(emb + (size_t)e * 768);
        const float4* xrp = (const float4*)(XF + (p / TOPK) * 768);
        float d = 0.0f;
#pragma unroll
        for (int t = 0; t < 24; t++) {
            float4 ev = er[q + (t << 3)];
            float4 xv = xrp[q + (t << 3)];
            d += ev.x * xv.x + ev.y * xv.y + ev.z * xv.z + ev.w * xv.w;
        }
        d += __shfl_xor_sync(0xffffffffu, d, 4);
        d += __shfl_xor_sync(0xffffffffu, d, 2);
        d += __shfl_xor_sync(0xffffffffu, d, 1);
        if (q == 0) EX[p] = d;
    }
    __syncthreads();

    if (tid < 32) {
        float ex[TOPK]; float mx = -1e30f;
#pragma unroll
        for (int j = 0; j < TOPK; j++) { ex[j] = EX[tid * TOPK + j]; mx = fmaxf(mx, ex[j]); }
        float se = 0.0f;
#pragma unroll
        for (int j = 0; j < TOPK; j++) { ex[j] = __expf(ex[j] - mx); se += ex[j]; }
        float inv = 1.0f / se;
        float best = -1e30f;
#pragma unroll
        for (int j = 0; j < TOPK; j++)
            best = fmaxf(best, 0.5f * (ex[j] * inv + CS[tid * TOPK + j]));
        out[t0 + tid] = best;
    }
}

extern "C" void kernel_launch(void* const* d_in, const int* in_sizes, int n_in,
                              void* d_out, int out_size) {
    const float* x   = (const float*)d_in[0];
    const float* emb = (const float*)d_in[1];
    if (n_in >= 2 && in_sizes[0] > in_sizes[1]) {   // embeddings is the larger tensor
        const float* t = x; x = emb; emb = t;
    }
    cudaFuncSetAttribute(main_kernel,  cudaFuncAttributeMaxDynamicSharedMemorySize, SMEM_MAIN);
    cudaFuncSetAttribute(final_kernel, cudaFuncAttributeMaxDynamicSharedMemorySize, SMEM_FIN);
    prep_kernel<<<VPAD / 48, 256>>>(emb);
    main_kernel<<<256, 256, SMEM_MAIN>>>(x);
    final_kernel<<<NTOK / 32, 256, SMEM_FIN>>>(x, emb, (float*)d_out);
}

// round 15
// speedup vs baseline: 1.7185x; 1.7185x over previous
#include <cuda_runtime.h>
#include <cuda_bf16.h>

// Problem constants
#define VOCAB  50257
#define VPAD   50688          // 99 * 512
#define HFULL  768
#define HR     192
#define TM     32             // tokens per block
#define TN     512            // vocab candidates per chunk
#define KC     16             // k-chunk
#define NKC    12             // 192/16
#define NCHUNK 99             // VPAD/TN
#define TOPK   10

// dynamic smem layout (float offsets)
#define OFF_XS 0              // [192][36]   x reduced, transposed, *4
#define OFF_BS 6912           // [2][16][512] double-buffered er chunk
#define OFF_LG 23296          // [256][68]   logits: 32 tok * 8 segments of 64(+4 pad)
#define SMEM_FLOATS 40704
#define SMEM_BYTES  (SMEM_FLOATS * 4)
// overlays (regions dead after GEMM loop)
#define OFF_MV 0              // [256][10] f   per-scanner top vals   (over XS)
#define OFF_MI 2560           // [256][10] i   per-scanner top idx
#define OFF_MS 5120           // [256]     f   per-scanner sumexp
#define OFF_XF 6912           // [32][768] f   full-dim x tile        (over BS+)
#define OFF_CI 31488          // [320] i       chosen indices         (over LG)
#define OFF_CS 31808          // [320] f       approx top scores
#define OFF_EX 32128          // [320] f       exact logits

// reduced embeddings, transposed [k][v], zero-padded to VPAD
__device__ float g_ert[(size_t)HR * VPAD];

__device__ __forceinline__ void cp16(float* s, const float* g) {
    unsigned sa = (unsigned)__cvta_generic_to_shared(s);
    asm volatile("cp.async.cg.shared.global [%0], [%1], 16;" :: "r"(sa), "l"(g));
}
__device__ __forceinline__ unsigned long long pack2(float v) {
    unsigned long long r;
    asm("mov.b64 %0, {%1, %2};" : "=l"(r) : "f"(v), "f"(v));
    return r;
}
__device__ __forceinline__ void fma2(unsigned long long& d, unsigned long long a, unsigned long long b) {
    asm("fma.rn.f32x2 %0, %1, %2, %0;" : "+l"(d) : "l"(a), "l"(b));
}

// Build g_ert[k][v] = emb[v][4k]  (strided reads through smem so global writes coalesce)
__global__ void __launch_bounds__(256)
prep_ert_kernel(const float* __restrict__ emb) {
    __shared__ float sm[48][193];
    const int vb = blockIdx.x * 48;
    for (int idx = threadIdx.x; idx < 48 * HR; idx += 256) {
        int vl = idx / HR, k = idx - vl * HR;
        int v = vb + vl;
        sm[vl][k] = (v < VOCAB) ? emb[(size_t)v * HFULL + 4 * k] : 0.0f;
    }
    __syncthreads();
    for (int idx = threadIdx.x; idx < 48 * HR; idx += 256) {
        int k = idx / 48, vl = idx - k * 48;
        g_ert[(size_t)k * VPAD + vb + vl] = sm[vl][k];
    }
}

__global__ void __launch_bounds__(256, 1)
main_kernel(const float* __restrict__ x, const float* __restrict__ emb,
            float* __restrict__ out) {
    extern __shared__ float sm[];
    float* XS = sm + OFF_XS;
    float* BS = sm + OFF_BS;
    float* LG = sm + OFF_LG;
    const int tid = threadIdx.x;
    const int ty = tid >> 6;        // 0..3  (8-token row group)
    const int tx = tid & 63;        // 0..63 (8-candidate col group)
    const int m0 = blockIdx.x * TM;

    // stage x reduced (transposed [k][m], scale 4 = sqrt(R)^2 folded in)
    for (int idx = tid; idx < TM * HR; idx += 256) {
        int m = idx / HR, k = idx - m * HR;
        XS[k * 36 + m] = 4.0f * x[(m0 + m) * HFULL + 4 * k];
    }

    // per-scanner top-k state: scanner = tid; token sM = tid>>3, segment sS = tid&7
    float tv[TOPK]; int ti[TOPK];
#pragma unroll
    for (int i = 0; i < TOPK; i++) { tv[i] = -1e30f; ti[i] = 0; }
    float minv = -1e30f; int minp = 0;
    float sumexp = 0.0f;
    const int sS = tid & 7, sM = tid >> 3;

    __syncthreads();

    // preload chunk 0, kc=0 into buffer 0
    {
        const float* src = g_ert;
#pragma unroll
        for (int i = 0; i < 8; i++) {
            int pos = i * 256 + tid;
            int r = pos >> 7, c4 = (pos & 127) << 2;
            cp16(BS + r * TN + c4, src + (size_t)r * VPAD + c4);
        }
        asm volatile("cp.async.commit_group;");
    }

    for (int ch = 0; ch < NCHUNK; ch++) {
        const int c0 = ch * TN;
        unsigned long long acc[8][4];
#pragma unroll
        for (int i = 0; i < 8; i++)
#pragma unroll
            for (int j = 0; j < 4; j++) acc[i][j] = 0ull;

        for (int kc = 0; kc < NKC; kc++) {
            if (kc + 1 < NKC) {
                const float* src = g_ert + (size_t)(kc + 1) * KC * VPAD + c0;
                float* dst = BS + ((kc + 1) & 1) * (KC * TN);
#pragma unroll
                for (int i = 0; i < 8; i++) {
                    int pos = i * 256 + tid;
                    int r = pos >> 7, c4 = (pos & 127) << 2;
                    cp16(dst + r * TN + c4, src + (size_t)r * VPAD + c4);
                }
                asm volatile("cp.async.commit_group;");
                asm volatile("cp.async.wait_group 1;");
            } else {
                asm volatile("cp.async.wait_group 0;");
            }
            __syncthreads();
            const float* Bp = BS + (kc & 1) * (KC * TN) + (tx << 3);
            const float* Ap = XS + kc * KC * 36 + (ty << 3);
#pragma unroll 4
            for (int k = 0; k < KC; k++) {
                const float4 a0 = *(const float4*)(Ap + k * 36);
                const float4 a1 = *(const float4*)(Ap + k * 36 + 4);
                const ulonglong2 b01 = *(const ulonglong2*)(Bp + (k << 9));
                const ulonglong2 b23 = *(const ulonglong2*)(Bp + (k << 9) + 4);
                unsigned long long bb[4] = {b01.x, b01.y, b23.x, b23.y};
                float av[8] = {a0.x, a0.y, a0.z, a0.w, a1.x, a1.y, a1.z, a1.w};
#pragma unroll
                for (int i = 0; i < 8; i++) {
                    unsigned long long ap = pack2(av[i]);
#pragma unroll
                    for (int j = 0; j < 4; j++) fma2(acc[i][j], ap, bb[j]);
                }
            }
            __syncthreads();
        }

        // prefetch next chunk's kc=0 into buffer 0 NOW, overlapping with spill+scan
        if (ch + 1 < NCHUNK) {
            const float* src = g_ert + (size_t)(ch + 1) * TN;
#pragma unroll
            for (int i = 0; i < 8; i++) {
                int pos = i * 256 + tid;
                int r = pos >> 7, c4 = (pos & 127) << 2;
                cp16(BS + r * TN + c4, src + (size_t)r * VPAD + c4);
            }
            asm volatile("cp.async.commit_group;");
        }

        // spill tile logits to smem (segmented layout for conflict-free scan)
#pragma unroll
        for (int i = 0; i < 8; i++) {
            int mrow = (ty << 3) + i;
            float* dst = LG + ((mrow << 3) + (tx >> 3)) * 68 + ((tx & 7) << 3);
            *(ulonglong2*)dst       = make_ulonglong2(acc[i][0], acc[i][1]);
            *(ulonglong2*)(dst + 4) = make_ulonglong2(acc[i][2], acc[i][3]);
        }
        __syncthreads();

        // scan: 8 scanners per token, 64 candidates each
        {
            const float* row = LG + ((sM << 3) + sS) * 68;
            const int gbase = c0 + (sS << 6);
            if (gbase + 64 <= VOCAB) {
#pragma unroll 4
                for (int c4 = 0; c4 < 16; c4++) {
                    float4 v = *(const float4*)(row + (c4 << 2));
                    sumexp += __expf(v.x) + __expf(v.y) + __expf(v.z) + __expf(v.w);
                    float vv[4] = {v.x, v.y, v.z, v.w};
#pragma unroll
                    for (int e = 0; e < 4; e++) {
                        if (vv[e] > minv) {
                            tv[minp] = vv[e]; ti[minp] = gbase + (c4 << 2) + e;
                            minv = tv[0]; minp = 0;
#pragma unroll
                            for (int q = 1; q < TOPK; q++)
                                if (tv[q] < minv) { minv = tv[q]; minp = q; }
                        }
                    }
                }
            } else {
                for (int c = 0; c < 64; c++) {
                    int gi = gbase + c;
                    if (gi < VOCAB) {
                        float l = row[c];
                        sumexp += __expf(l);
                        if (l > minv) {
                            tv[minp] = l; ti[minp] = gi;
                            minv = tv[0]; minp = 0;
#pragma unroll
                            for (int q = 1; q < TOPK; q++)
                                if (tv[q] < minv) { minv = tv[q]; minp = q; }
                        }
                    }
                }
            }
        }
        __syncthreads();
    }

    // dump per-scanner state (scanner index == tid)
    float* MV = sm + OFF_MV;
    int*   MI = (int*)(sm + OFF_MI);
    float* MS = sm + OFF_MS;
#pragma unroll
    for (int i = 0; i < TOPK; i++) { MV[tid * TOPK + i] = tv[i]; MI[tid * TOPK + i] = ti[i]; }
    MS[tid] = sumexp;
    __syncthreads();

    float* XF = sm + OFF_XF;
    int*   CI = (int*)(sm + OFF_CI);
    float* CS = sm + OFF_CS;
    float* EX = sm + OFF_EX;

    // merge 8 scanner lists per token -> global top-10 + softmax denominator
    if (tid < TM) {
        const int m = tid;
        float bv[TOPK]; int bi[TOPK];
#pragma unroll
        for (int i = 0; i < TOPK; i++) { bv[i] = -1e30f; bi[i] = 0; }
        float bmin = -1e30f; int bmp = 0;
        for (int e = 0; e < 8 * TOPK; e++) {
            float v = MV[m * 80 + e];
            if (v > bmin) {
                bv[bmp] = v; bi[bmp] = MI[m * 80 + e];
                bmin = bv[0]; bmp = 0;
#pragma unroll
                for (int q = 1; q < TOPK; q++)
                    if (bv[q] < bmin) { bmin = bv[q]; bmp = q; }
            }
        }
        float S = 0.0f;
#pragma unroll
        for (int s = 0; s < 8; s++) S += MS[m * 8 + s];
        float invS = 1.0f / S;
#pragma unroll
        for (int j = 0; j < TOPK; j++) {
            CI[m * TOPK + j] = bi[j];
            CS[m * TOPK + j] = __expf(bv[j]) * invS;
        }
    }
    __syncthreads();

    // stage full-dim x tile
    for (int idx = tid; idx < TM * HFULL; idx += 256)
        XF[idx] = x[m0 * HFULL + idx];
    __syncthreads();

    // exact rescore: 320 (token,cand) pairs, 8 lanes per pair, coalesced gather
#pragma unroll 1
    for (int it = 0; it < 10; it++) {
        int slot = it * 256 + tid;
        int p = slot >> 3, q = slot & 7;
        int e = CI[p];
        const float4* er = (const float4*)(emb + (size_t)e * HFULL);
        const float4* xr = (const float4*)(XF + (p / TOPK) * HFULL);
        float d = 0.0f;
#pragma unroll
        for (int t = 0; t < 24; t++) {
            float4 ev = er[q + (t << 3)];
            float4 xv = xr[q + (t << 3)];
            d += ev.x * xv.x + ev.y * xv.y + ev.z * xv.z + ev.w * xv.w;
        }
        d += __shfl_xor_sync(0xffffffffu, d, 4);
        d += __shfl_xor_sync(0xffffffffu, d, 2);
        d += __shfl_xor_sync(0xffffffffu, d, 1);
        if (q == 0) EX[p] = d;
    }
    __syncthreads();

    // finalize: softmax over 10 exact logits, combine with approx scores, max
    if (tid < TM) {
        const int m = tid;
        float ex[TOPK];
        float mx = -1e30f;
#pragma unroll
        for (int j = 0; j < TOPK; j++) { ex[j] = EX[m * TOPK + j]; mx = fmaxf(mx, ex[j]); }
        float se = 0.0f;
#pragma unroll
        for (int j = 0; j < TOPK; j++) { ex[j] = __expf(ex[j] - mx); se += ex[j]; }
        float inv = 1.0f / se;
        float best = -1e30f;
#pragma unroll
        for (int j = 0; j < TOPK; j++)
            best = fmaxf(best, 0.5f * (ex[j] * inv + CS[m * TOPK + j]));
        out[m0 + m] = best;
    }
}

extern "C" void kernel_launch(void* const* d_in, const int* in_sizes, int n_in,
                              void* d_out, int out_size) {
    const float* x   = (const float*)d_in[0];
    const float* emb = (const float*)d_in[1];
    if (n_in >= 2 && in_sizes[0] > in_sizes[1]) {   // embeddings is the larger tensor
        const float* t = x; x = emb; emb = t;
    }
    cudaFuncSetAttribute(main_kernel, cudaFuncAttributeMaxDynamicSharedMemorySize, SMEM_BYTES);
    prep_ert_kernel<<<VPAD / 48, 256>>>(emb);
    main_kernel<<<4096 / TM, 256, SMEM_BYTES>>>(x, emb, (float*)d_out);
}

// round 17
// speedup vs baseline: 1.8112x; 1.0539x over previous
#include <cuda_runtime.h>
#include <cuda_bf16.h>

// Problem constants
#define VOCAB  50257
#define VPAD   50688          // 99 * 512
#define HFULL  768
#define HR     192
#define TM     32             // tokens per block
#define TN     512            // vocab candidates per chunk
#define KC     16             // k-chunk
#define NKC    12             // 192/16
#define NCHUNK 99             // VPAD/TN
#define TOPK   10

// dynamic smem layout (float offsets)
#define OFF_XS 0              // [192][36]   x reduced, transposed, *4
#define OFF_BS 6912           // [2][16][512] double-buffered er chunk
#define OFF_LG 23296          // [256][68]   logits: 32 tok * 8 segments of 64(+4 pad)
#define SMEM_FLOATS 40704
#define SMEM_BYTES  (SMEM_FLOATS * 4)
// overlays (regions dead after GEMM loop)
#define OFF_MV 0              // [256][10] f   per-scanner top vals   (over XS)
#define OFF_MI 2560           // [256][10] i   per-scanner top idx
#define OFF_MS 5120           // [256]     f   per-scanner sumexp
#define OFF_XF 6912           // [32][768] f   full-dim x tile        (over BS+)
#define OFF_CI 31488          // [320] i       chosen indices         (over LG)
#define OFF_CS 31808          // [320] f       approx top scores
#define OFF_EX 32128          // [320] f       exact logits

// reduced embeddings, transposed [k][v], zero-padded to VPAD
__device__ float g_ert[(size_t)HR * VPAD];

__device__ __forceinline__ void cp16(float* s, const float* g) {
    unsigned sa = (unsigned)__cvta_generic_to_shared(s);
    asm volatile("cp.async.cg.shared.global [%0], [%1], 16;" :: "r"(sa), "l"(g));
}
__device__ __forceinline__ unsigned long long pack2(float v) {
    unsigned long long r;
    asm("mov.b64 %0, {%1, %2};" : "=l"(r) : "f"(v), "f"(v));
    return r;
}
__device__ __forceinline__ void fma2(unsigned long long& d, unsigned long long a, unsigned long long b) {
    asm("fma.rn.f32x2 %0, %1, %2, %0;" : "+l"(d) : "l"(a), "l"(b));
}

// Build g_ert[k][v] = emb[v][4k]  (strided reads through smem so global writes coalesce)
__global__ void __launch_bounds__(256)
prep_ert_kernel(const float* __restrict__ emb) {
    __shared__ float sm[48][193];
    const int vb = blockIdx.x * 48;
    for (int idx = threadIdx.x; idx < 48 * HR; idx += 256) {
        int vl = idx / HR, k = idx - vl * HR;
        int v = vb + vl;
        sm[vl][k] = (v < VOCAB) ? emb[(size_t)v * HFULL + 4 * k] : 0.0f;
    }
    __syncthreads();
    for (int idx = threadIdx.x; idx < 48 * HR; idx += 256) {
        int k = idx / 48, vl = idx - k * 48;
        g_ert[(size_t)k * VPAD + vb + vl] = sm[vl][k];
    }
}

__global__ void __launch_bounds__(256, 1)
main_kernel(const float* __restrict__ x, const float* __restrict__ emb,
            float* __restrict__ out) {
    extern __shared__ float sm[];
    float* XS = sm + OFF_XS;
    float* BS = sm + OFF_BS;
    float* LG = sm + OFF_LG;
    const int tid = threadIdx.x;
    const int ty = tid >> 6;        // 0..3  (8-token row group)
    const int tx = tid & 63;        // 0..63
    const int m0 = blockIdx.x * TM;

    // stage x reduced (transposed [k][m], scale 4 = sqrt(R)^2 folded in)
    for (int idx = tid; idx < TM * HR; idx += 256) {
        int m = idx / HR, k = idx - m * HR;
        XS[k * 36 + m] = 4.0f * x[(m0 + m) * HFULL + 4 * k];
    }

    // per-scanner top-k state: scanner = tid; token sM = tid>>3, segment sS = tid&7
    float tv[TOPK]; int ti[TOPK];
#pragma unroll
    for (int i = 0; i < TOPK; i++) { tv[i] = -1e30f; ti[i] = 0; }
    float minv = -1e30f; int minp = 0;
    float sumexp = 0.0f;
    const int sS = tid & 7, sM = tid >> 3;

    __syncthreads();

    // preload chunk 0, kc=0 into buffer 0
    {
        const float* src = g_ert;
#pragma unroll
        for (int i = 0; i < 8; i++) {
            int pos = i * 256 + tid;
            int r = pos >> 7, c4 = (pos & 127) << 2;
            cp16(BS + r * TN + c4, src + (size_t)r * VPAD + c4);
        }
        asm volatile("cp.async.commit_group;");
    }

    for (int ch = 0; ch < NCHUNK; ch++) {
        const int c0 = ch * TN;
        // acc[i][0..1] -> cands 4tx..4tx+3 ; acc[i][2..3] -> cands 256+4tx..256+4tx+3
        unsigned long long acc[8][4];
#pragma unroll
        for (int i = 0; i < 8; i++)
#pragma unroll
            for (int j = 0; j < 4; j++) acc[i][j] = 0ull;

        for (int kc = 0; kc < NKC; kc++) {
            if (kc + 1 < NKC) {
                const float* src = g_ert + (size_t)(kc + 1) * KC * VPAD + c0;
                float* dst = BS + ((kc + 1) & 1) * (KC * TN);
#pragma unroll
                for (int i = 0; i < 8; i++) {
                    int pos = i * 256 + tid;
                    int r = pos >> 7, c4 = (pos & 127) << 2;
                    cp16(dst + r * TN + c4, src + (size_t)r * VPAD + c4);
                }
                asm volatile("cp.async.commit_group;");
                asm volatile("cp.async.wait_group 1;");
            } else {
                asm volatile("cp.async.wait_group 0;");
            }
            __syncthreads();
            const float* Bp = BS + (kc & 1) * (KC * TN) + (tx << 2);   // 16B/lane: conflict-free
            const float* Ap = XS + kc * KC * 36 + (ty << 3);
#pragma unroll 4
            for (int k = 0; k < KC; k++) {
                const float4 a0 = *(const float4*)(Ap + k * 36);
                const float4 a1 = *(const float4*)(Ap + k * 36 + 4);
                const ulonglong2 b01 = *(const ulonglong2*)(Bp + (k << 9));        // cands 4tx..+3
                const ulonglong2 b23 = *(const ulonglong2*)(Bp + (k << 9) + 256);  // cands 256+4tx..+3
                unsigned long long bb[4] = {b01.x, b01.y, b23.x, b23.y};
                float av[8] = {a0.x, a0.y, a0.z, a0.w, a1.x, a1.y, a1.z, a1.w};
#pragma unroll
                for (int i = 0; i < 8; i++) {
                    unsigned long long ap = pack2(av[i]);
#pragma unroll
                    for (int j = 0; j < 4; j++) fma2(acc[i][j], ap, bb[j]);
                }
            }
            __syncthreads();
        }

        // prefetch next chunk's kc=0 into buffer 0, overlapping with spill+scan
        if (ch + 1 < NCHUNK) {
            const float* src = g_ert + (size_t)(ch + 1) * TN;
#pragma unroll
            for (int i = 0; i < 8; i++) {
                int pos = i * 256 + tid;
                int r = pos >> 7, c4 = (pos & 127) << 2;
                cp16(BS + r * TN + c4, src + (size_t)r * VPAD + c4);
            }
            asm volatile("cp.async.commit_group;");
        }

        // spill tile logits to smem (segmented layout for conflict-free scan)
        // low group: cols 4tx..4tx+3   -> segment tx>>4,     offset (4tx)&63
        // high group: cols 256+4tx..+3 -> segment 4+(tx>>4), same offset
        {
            const int seg_lo = tx >> 4;
            const int off_c  = (tx << 2) & 63;
#pragma unroll
            for (int i = 0; i < 8; i++) {
                int mrow = (ty << 3) + i;
                float* d_lo = LG + (((mrow << 3) + seg_lo) * 68) + off_c;
                float* d_hi = LG + (((mrow << 3) + 4 + seg_lo) * 68) + off_c;
                *(ulonglong2*)d_lo = make_ulonglong2(acc[i][0], acc[i][1]);
                *(ulonglong2*)d_hi = make_ulonglong2(acc[i][2], acc[i][3]);
            }
        }
        __syncthreads();

        // scan: 8 scanners per token, 64 candidates each
        {
            const float* row = LG + ((sM << 3) + sS) * 68;
            const int gbase = c0 + (sS << 6);
            if (gbase + 64 <= VOCAB) {
#pragma unroll 4
                for (int c4 = 0; c4 < 16; c4++) {
                    float4 v = *(const float4*)(row + (c4 << 2));
                    sumexp += __expf(v.x) + __expf(v.y) + __expf(v.z) + __expf(v.w);
                    float vv[4] = {v.x, v.y, v.z, v.w};
#pragma unroll
                    for (int e = 0; e < 4; e++) {
                        if (vv[e] > minv) {
                            tv[minp] = vv[e]; ti[minp] = gbase + (c4 << 2) + e;
                            minv = tv[0]; minp = 0;
#pragma unroll
                            for (int q = 1; q < TOPK; q++)
                                if (tv[q] < minv) { minv = tv[q]; minp = q; }
                        }
                    }
                }
            } else {
                for (int c = 0; c < 64; c++) {
                    int gi = gbase + c;
                    if (gi < VOCAB) {
                        float l = row[c];
                        sumexp += __expf(l);
                        if (l > minv) {
                            tv[minp] = l; ti[minp] = gi;
                            minv = tv[0]; minp = 0;
#pragma unroll
                            for (int q = 1; q < TOPK; q++)
                                if (tv[q] < minv) { minv = tv[q]; minp = q; }
                        }
                    }
                }
            }
        }
        __syncthreads();
    }

    // dump per-scanner state (scanner index == tid)
    float* MV = sm + OFF_MV;
    int*   MI = (int*)(sm + OFF_MI);
    float* MS = sm + OFF_MS;
#pragma unroll
    for (int i = 0; i < TOPK; i++) { MV[tid * TOPK + i] = tv[i]; MI[tid * TOPK + i] = ti[i]; }
    MS[tid] = sumexp;
    __syncthreads();

    float* XF = sm + OFF_XF;
    int*   CI = (int*)(sm + OFF_CI);
    float* CS = sm + OFF_CS;
    float* EX = sm + OFF_EX;

    // merge 8 scanner lists per token -> global top-10 + softmax denominator
    if (tid < TM) {
        const int m = tid;
        float bv[TOPK]; int bi[TOPK];
#pragma unroll
        for (int i = 0; i < TOPK; i++) { bv[i] = -1e30f; bi[i] = 0; }
        float bmin = -1e30f; int bmp = 0;
        for (int e = 0; e < 8 * TOPK; e++) {
            float v = MV[m * 80 + e];
            if (v > bmin) {
                bv[bmp] = v; bi[bmp] = MI[m * 80 + e];
                bmin = bv[0]; bmp = 0;
#pragma unroll
                for (int q = 1; q < TOPK; q++)
                    if (bv[q] < bmin) { bmin = bv[q]; bmp = q; }
            }
        }
        float S = 0.0f;
#pragma unroll
        for (int s = 0; s < 8; s++) S += MS[m * 8 + s];
        float invS = 1.0f / S;
#pragma unroll
        for (int j = 0; j < TOPK; j++) {
            CI[m * TOPK + j] = bi[j];
            CS[m * TOPK + j] = __expf(bv[j]) * invS;
        }
    }
    __syncthreads();

    // stage full-dim x tile
    for (int idx = tid; idx < TM * HFULL; idx += 256)
        XF[idx] = x[m0 * HFULL + idx];
    __syncthreads();

    // exact rescore: 320 (token,cand) pairs, 8 lanes per pair, coalesced gather
#pragma unroll 1
    for (int it = 0; it < 10; it++) {
        int slot = it * 256 + tid;
        int p = slot >> 3, q = slot & 7;
        int e = CI[p];
        const float4* er = (const float4*)(emb + (size_t)e * HFULL);
        const float4* xr = (const float4*)(XF + (p / TOPK) * HFULL);
        float d = 0.0f;
#pragma unroll
        for (int t = 0; t < 24; t++) {
            float4 ev = er[q + (t << 3)];
            float4 xv = xr[q + (t << 3)];
            d += ev.x * xv.x + ev.y * xv.y + ev.z * xv.z + ev.w * xv.w;
        }
        d += __shfl_xor_sync(0xffffffffu, d, 4);
        d += __shfl_xor_sync(0xffffffffu, d, 2);
        d += __shfl_xor_sync(0xffffffffu, d, 1);
        if (q == 0) EX[p] = d;
    }
    __syncthreads();

    // finalize: softmax over 10 exact logits, combine with approx scores, max
    if (tid < TM) {
        const int m = tid;
        float ex[TOPK];
        float mx = -1e30f;
#pragma unroll
        for (int j = 0; j < TOPK; j++) { ex[j] = EX[m * TOPK + j]; mx = fmaxf(mx, ex[j]); }
        float se = 0.0f;
#pragma unroll
        for (int j = 0; j < TOPK; j++) { ex[j] = __expf(ex[j] - mx); se += ex[j]; }
        float inv = 1.0f / se;
        float best = -1e30f;
#pragma unroll
        for (int j = 0; j < TOPK; j++)
            best = fmaxf(best, 0.5f * (ex[j] * inv + CS[m * TOPK + j]));
        out[m0 + m] = best;
    }
}

extern "C" void kernel_launch(void* const* d_in, const int* in_sizes, int n_in,
                              void* d_out, int out_size) {
    const float* x   = (const float*)d_in[0];
    const float* emb = (const float*)d_in[1];
    if (n_in >= 2 && in_sizes[0] > in_sizes[1]) {   // embeddings is the larger tensor
        const float* t = x; x = emb; emb = t;
    }
    cudaFuncSetAttribute(main_kernel, cudaFuncAttributeMaxDynamicSharedMemorySize, SMEM_BYTES);
    prep_ert_kernel<<<VPAD / 48, 256>>>(emb);
    main_kernel<<<4096 / TM, 256, SMEM_BYTES>>>(x, emb, (float*)d_out);
}